// round 7
// baseline (speedup 1.0000x reference)
#include <cuda_runtime.h>
#include <cuda_bf16.h>
#include <cstdint>

// Problem dims
#define NB   32
#define C    256
#define H    56
#define W    56
#define HP   58
#define WP   58
#define MP   (NB*HP*WP)        // 107648 padded-flat rows
#define MPAD 384               // tile overrun (128) + tap offset (118), padded
#define NVALID (NB*H*W)        // 100352

// GEMM tiling (int8 IMMA path)
#define BM 128
#define BN 128
#define BKB 128                // k-bytes per pipeline chunk (one SW128 row)
#define NS 3                   // cp.async pipeline stages
#define CHUNKS 18              // 9 taps * 2 k-chunks of 128
#define STAGE_BYTES 32768      // A 128x128B + B 128x128B
#define DYNSMEM (NS*STAGE_BYTES)

// -------- device scratch (no allocations allowed) --------
__device__ __align__(1024) char  g_xb[(size_t)(MP + MPAD) * C];   // padded NHWC binarized x (+-1 int8)
__device__ __align__(1024) char  g_wb[9 * 256 * 256];             // [tap][cout][cin] int8
__device__ __align__(1024) short g_y[(size_t)(MP + MPAD) * 256];  // conv result (exact ints)
__device__ int       g_sum[256];
__device__ long long g_sumsq[256];
__device__ float     g_scale[256];
__device__ float     g_shift[256];

// -------- asm helpers --------
__device__ __forceinline__ uint32_t smem_u32(const void* p) {
    return (uint32_t)__cvta_generic_to_shared(p);
}
__device__ __forceinline__ void ldsm4(uint32_t& r0, uint32_t& r1, uint32_t& r2, uint32_t& r3, uint32_t a) {
    asm volatile("ldmatrix.sync.aligned.m8n8.x4.shared.b16 {%0,%1,%2,%3}, [%4];"
                 : "=r"(r0), "=r"(r1), "=r"(r2), "=r"(r3) : "r"(a));
}
// int8 tensor-core MMA: D(s32) += A(s8,16x32) * B(s8,32x8)
__device__ __forceinline__ void imma16832(int* d, const uint32_t* a, uint32_t b0, uint32_t b1) {
    asm volatile("mma.sync.aligned.m16n8k32.row.col.s32.s8.s8.s32 "
                 "{%0,%1,%2,%3},{%4,%5,%6,%7},{%8,%9},{%0,%1,%2,%3};"
                 : "+r"(d[0]), "+r"(d[1]), "+r"(d[2]), "+r"(d[3])
                 : "r"(a[0]), "r"(a[1]), "r"(a[2]), "r"(a[3]), "r"(b0), "r"(b1));
}
__device__ __forceinline__ void cpasync16(uint32_t dst, const void* src) {
    asm volatile("cp.async.cg.shared.global [%0], [%1], 16;" :: "r"(dst), "l"(src));
}
__device__ __forceinline__ void cpcommit() { asm volatile("cp.async.commit_group;"); }
template <int N> __device__ __forceinline__ void cpwait() { asm volatile("cp.async.wait_group %0;" :: "n"(N)); }

// -------- kernel 0: zero scratch (xb borders/pad + stats) --------
__global__ void zero_kernel() {
    size_t i = (size_t)blockIdx.x * blockDim.x + threadIdx.x;
    const size_t nchunk = ((size_t)(MP + MPAD) * C) / 16;   // bytes/16
    if (i < nchunk) reinterpret_cast<float4*>(g_xb)[i] = make_float4(0.f, 0.f, 0.f, 0.f);
    if (i < 256) { g_sum[i] = 0; g_sumsq[i] = 0; }
}

// -------- kernel 1: binarize+transpose x NCHW(f32) -> padded NHWC(int8 +-1) --------
__global__ void pack_x_kernel(const float* __restrict__ x) {
    __shared__ char t[32][33];
    const int tx = threadIdx.x, ty = threadIdx.y;
    const int bz = blockIdx.z;              // n*56 + h
    const int n = bz / 56, h = bz % 56;
    const int w0 = blockIdx.x * 32, c0 = blockIdx.y * 32;
#pragma unroll
    for (int j = 0; j < 4; j++) {
        int c = c0 + ty + j * 8;
        int w = w0 + tx;
        if (w < W) {
            float v = x[(((size_t)n * C + c) * H + h) * W + w];
            t[ty + j * 8][tx] = (v >= 0.f) ? (char)1 : (char)-1;
        }
    }
    __syncthreads();
#pragma unroll
    for (int j = 0; j < 4; j++) {
        int wl = ty + j * 8;
        int w = w0 + wl;
        if (w < W) {
            int c = c0 + tx;
            g_xb[(((size_t)(n * HP + h + 1)) * WP + (w + 1)) * C + c] = t[tx][wl];
        }
    }
}

// -------- kernel 2: binarize w OIHW -> [tap][cout][cin] int8 --------
__global__ void pack_w_kernel(const float* __restrict__ w) {
    int g = blockIdx.x * blockDim.x + threadIdx.x;     // co*256+ci
    if (g >= 65536) return;
    const float* wp = w + (size_t)g * 9;
#pragma unroll
    for (int t = 0; t < 9; t++) {
        g_wb[(size_t)t * 65536 + g] = (wp[t] >= 0.f) ? (char)1 : (char)-1;
    }
}

// -------- kernel 3: implicit-GEMM binary conv (int8 IMMA, 3-stage cp.async) --------
__global__ void __launch_bounds__(256, 2) conv_kernel() {
    extern __shared__ __align__(1024) char sm[];   // NS stages: [A 16KB | B 16KB]
    const int tid = threadIdx.x;
    const int lane = tid & 31;
    const int warp = tid >> 5;
    const int wm = warp & 1;       // 2 warps along M (64 rows each)
    const int wn = warp >> 1;      // 4 warps along N (32 cols each)
    const size_t mbase = (size_t)blockIdx.x * BM;
    const int nbase = blockIdx.y * BN;

    int acc[4][4][4];
#pragma unroll
    for (int a = 0; a < 4; a++)
#pragma unroll
        for (int b = 0; b < 4; b++)
#pragma unroll
            for (int c = 0; c < 4; c++) acc[a][b][c] = 0;

    const uint32_t smbase = smem_u32(sm);

    // producer: all 256 threads; per stage 2048 x 16B (A then B)
    auto issue_stage = [&](int s, int it) {
        const int t = it >> 1;                 // tap 0..8
        const int kc = (it & 1) * BKB;         // k-byte offset within 256
        const int off = (t / 3) * WP + (t % 3);
        const uint32_t stA = smbase + (uint32_t)s * STAGE_BYTES;
        const uint32_t stB = stA + 16384u;
        const char* gA = g_xb + (mbase + (size_t)off) * 256 + kc;
        const char* gB = g_wb + (size_t)t * 65536 + (size_t)nbase * 256 + kc;
#pragma unroll
        for (int i = 0; i < 4; ++i) {
            int q = i * 256 + tid;             // 0..1023
            int row = q >> 3, c16 = q & 7;
            uint32_t dsto = (uint32_t)(row * 128 + ((c16 ^ (row & 7)) * 16));
            cpasync16(stA + dsto, gA + (size_t)row * 256 + c16 * 16);
        }
#pragma unroll
        for (int i = 0; i < 4; ++i) {
            int q = i * 256 + tid;
            int row = q >> 3, c16 = q & 7;
            uint32_t dsto = (uint32_t)(row * 128 + ((c16 ^ (row & 7)) * 16));
            cpasync16(stB + dsto, gB + (size_t)row * 256 + c16 * 16);
        }
        cpcommit();
    };

    issue_stage(0, 0);
    issue_stage(1, 1);

    for (int it = 0; it < CHUNKS; ++it) {
        const int s = it % NS;
        if (it + 2 < CHUNKS) { issue_stage((it + 2) % NS, it + 2); cpwait<2>(); }
        else if (it + 1 < CHUNKS) { cpwait<1>(); }
        else { cpwait<0>(); }
        __syncthreads();

        const uint32_t stA = smbase + (uint32_t)s * STAGE_BYTES;
        const uint32_t stB = stA + 16384u;
#pragma unroll
        for (int kf = 0; kf < 4; ++kf) {
            uint32_t a[4][4], b[2][4];
            const int chunk = kf * 2 + (lane >> 4);     // 16B chunk index 0..7
#pragma unroll
            for (int mf = 0; mf < 4; ++mf) {
                int row = wm * 64 + mf * 16 + (lane & 15);
                ldsm4(a[mf][0], a[mf][1], a[mf][2], a[mf][3],
                      stA + (uint32_t)(row * 128 + ((chunk ^ (row & 7)) * 16)));
            }
#pragma unroll
            for (int nh = 0; nh < 2; ++nh) {
                int row = wn * 32 + nh * 16 + (lane & 15);
                ldsm4(b[nh][0], b[nh][1], b[nh][2], b[nh][3],
                      stB + (uint32_t)(row * 128 + ((chunk ^ (row & 7)) * 16)));
            }
#pragma unroll
            for (int mf = 0; mf < 4; ++mf)
#pragma unroll
                for (int nf = 0; nf < 4; ++nf) {
                    int nh = nf >> 1, sel = nf & 1;
                    imma16832(acc[mf][nf], a[mf], b[nh][sel], b[nh][sel | 2]);
                }
        }
        __syncthreads();
    }

    // epilogue: exact integer conv results -> int16 [m][cout]
#pragma unroll
    for (int mf = 0; mf < 4; ++mf) {
        size_t m0 = mbase + wm * 64 + mf * 16 + (lane >> 2);
#pragma unroll
        for (int nf = 0; nf < 4; ++nf) {
            int co = nbase + wn * 32 + nf * 8 + (lane & 3) * 2;
            short2 v0 = make_short2((short)acc[mf][nf][0], (short)acc[mf][nf][1]);
            short2 v1 = make_short2((short)acc[mf][nf][2], (short)acc[mf][nf][3]);
            *reinterpret_cast<short2*>(&g_y[m0 * 256 + co]) = v0;
            *reinterpret_cast<short2*>(&g_y[(m0 + 8) * 256 + co]) = v1;
        }
    }
}

// -------- kernel 4: per-channel integer sums over VALID pixels (deterministic) --------
__global__ void stats_kernel() {
    const int co = threadIdx.x;          // 256 threads = 256 channels
    const int b = blockIdx.x;            // 256 blocks x 392 rows
    int sum = 0;
    long long sq = 0;
    for (int r = 0; r < 392; r++) {
        int v = b * 392 + r;
        int n = v / 3136;
        int rem = v - n * 3136;
        int h = rem / 56;
        int w = rem - h * 56;
        size_t m = ((size_t)(n * HP + h)) * WP + w;
        int s = g_y[m * 256 + co];
        sum += s;
        sq += (long long)(s * s);
    }
    atomicAdd(&g_sum[co], sum);
    atomicAdd(reinterpret_cast<unsigned long long*>(&g_sumsq[co]), (unsigned long long)sq);
}

// -------- kernel 5: finalize BN params --------
__global__ void finalize_kernel(const float* __restrict__ gamma, const float* __restrict__ beta) {
    int c = threadIdx.x;
    const double n = (double)NVALID;
    double mean = (double)g_sum[c] / n;
    double var = (double)g_sumsq[c] / n - mean * mean;
    float inv = rsqrtf((float)var + 1e-5f);
    float sc = gamma[c] * inv;
    g_scale[c] = sc;
    g_shift[c] = beta[c] - (float)mean * sc;
}

// -------- kernel 6: normalize + transpose [m][cout] -> NCHW f32 output --------
__global__ void normalize_kernel(float* __restrict__ out) {
    __shared__ float t[32][33];
    const int tx = threadIdx.x, ty = threadIdx.y;
    const int bz = blockIdx.z;            // n*56 + h
    const int n = bz / 56, h = bz % 56;
    const int w0 = blockIdx.x * 32, c0 = blockIdx.y * 32;
    const size_t m0 = ((size_t)(n * HP + h)) * WP;
#pragma unroll
    for (int j = 0; j < 4; j++) {
        int wl = ty + j * 8;
        int w = w0 + wl;
        if (w < W) {
            t[wl][tx] = (float)g_y[(m0 + w) * 256 + c0 + tx];
        }
    }
    __syncthreads();
#pragma unroll
    for (int j = 0; j < 4; j++) {
        int cl = ty + j * 8;
        int c = c0 + cl;
        int w = w0 + tx;
        if (w < W) {
            out[(((size_t)n * C + c) * H + h) * W + w] = t[tx][cl] * g_scale[c] + g_shift[c];
        }
    }
}

extern "C" void kernel_launch(void* const* d_in, const int* in_sizes, int n_in,
                              void* d_out, int out_size) {
    const float* x     = (const float*)d_in[0];
    const float* w     = (const float*)d_in[1];
    const float* gamma = (const float*)d_in[2];
    const float* beta  = (const float*)d_in[3];
    float* out = (float*)d_out;
    (void)in_sizes; (void)n_in; (void)out_size;

    // 0) zero xb (borders + pad + tile overrun) and stats accumulators
    {
        const size_t nchunk = ((size_t)(MP + MPAD) * C) / 16;
        int blocks = (int)((nchunk + 255) / 256);
        zero_kernel<<<blocks, 256>>>();
    }
    // 1) binarize/pad/transpose x
    {
        dim3 grid(2, 8, NB * H);
        dim3 block(32, 8);
        pack_x_kernel<<<grid, block>>>(x);
    }
    // 2) binarize w
    pack_w_kernel<<<256, 256>>>(w);
    // 3) conv (int8 IMMA implicit GEMM, 3-stage pipeline)
    {
        static bool attr_set = false;
        if (!attr_set) {
            cudaFuncSetAttribute(conv_kernel, cudaFuncAttributeMaxDynamicSharedMemorySize, DYNSMEM);
            attr_set = true;
        }
        dim3 grid(MP / BM, 256 / BN);   // 841 x 2
        conv_kernel<<<grid, 256, DYNSMEM>>>();
    }
    // 4) per-channel sums
    stats_kernel<<<256, 256>>>();
    // 5) BN params
    finalize_kernel<<<1, 256>>>(gamma, beta);
    // 6) normalize + layout back to NCHW
    {
        dim3 grid(2, 8, NB * H);
        dim3 block(32, 8);
        normalize_kernel<<<grid, block>>>(out);
    }
}

// round 12
// speedup vs baseline: 2.0324x; 2.0324x over previous
#include <cuda_runtime.h>
#include <cuda_bf16.h>
#include <cstdint>

// Problem dims
#define NB   32
#define C    256
#define H    56
#define W    56
#define HP   58
#define WP   58
#define MP   (NB*HP*WP)        // 107648 padded-flat rows (841*128)
#define MPAD 384               // overrun rows for tap offsets (max 118)
#define NVALID (NB*H*W)        // 100352

// GEMM tiling (bf16 HMMA path)
#define BM 128
#define BN 128
#define BKE 64                 // k-elements per chunk (=128 bytes bf16)
#define NS 3                   // cp.async pipeline stages
#define CHUNKS 36              // 9 taps * 4 k-chunks of 64
#define STAGE_BYTES 32768      // A 128x128B + B 128x128B
#define DYNSMEM (NS*STAGE_BYTES)

// -------- device scratch (no allocations allowed) --------
__device__ __align__(1024) __nv_bfloat16 g_xb[(size_t)(MP + MPAD) * C];  // padded NHWC +-1
__device__ __align__(1024) __nv_bfloat16 g_wb[9 * 256 * 256];            // [tap][cout][cin]
__device__ __align__(1024) short g_y[(size_t)MP * 256];                  // conv result (exact ints)
__device__ int       g_sum[256];
__device__ long long g_sumsq[256];
__device__ float     g_scale[256];
__device__ float     g_shift[256];

// -------- asm helpers --------
__device__ __forceinline__ uint32_t smem_u32(const void* p) {
    return (uint32_t)__cvta_generic_to_shared(p);
}
__device__ __forceinline__ void ldsm4(uint32_t& r0, uint32_t& r1, uint32_t& r2, uint32_t& r3, uint32_t a) {
    asm volatile("ldmatrix.sync.aligned.m8n8.x4.shared.b16 {%0,%1,%2,%3}, [%4];"
                 : "=r"(r0), "=r"(r1), "=r"(r2), "=r"(r3) : "r"(a));
}
__device__ __forceinline__ void mma16816(float* d, const uint32_t* a, uint32_t b0, uint32_t b1) {
    asm volatile("mma.sync.aligned.m16n8k16.row.col.f32.bf16.bf16.f32 "
                 "{%0,%1,%2,%3},{%4,%5,%6,%7},{%8,%9},{%0,%1,%2,%3};"
                 : "+f"(d[0]), "+f"(d[1]), "+f"(d[2]), "+f"(d[3])
                 : "r"(a[0]), "r"(a[1]), "r"(a[2]), "r"(a[3]), "r"(b0), "r"(b1));
}
__device__ __forceinline__ void cpasync16(uint32_t dst, const void* src) {
    asm volatile("cp.async.cg.shared.global [%0], [%1], 16;" :: "r"(dst), "l"(src));
}
__device__ __forceinline__ void cpcommit() { asm volatile("cp.async.commit_group;"); }
template <int N> __device__ __forceinline__ void cpwait() { asm volatile("cp.async.wait_group %0;" :: "n"(N)); }

// -------- kernel 0: zero ONLY border/pad rows of xb + stats (interior overwritten by pack_x) --------
// Border rows per image: h'=0 (58), h'=57 (58), w'=0 (56), w'=57 (56) => 228. Plus MPAD overrun rows.
#define BROWS_PER_IMG 228
#define BROWS_TOTAL (NB*BROWS_PER_IMG + MPAD)     // 7680
__global__ void zero_border_kernel() {
    const int warp = threadIdx.x >> 5;
    const int lane = threadIdx.x & 31;
    const int r = blockIdx.x * 8 + warp;          // border-row index
    if (r < BROWS_TOTAL) {
        size_t row;
        if (r >= NB * BROWS_PER_IMG) {
            row = (size_t)MP + (r - NB * BROWS_PER_IMG);
        } else {
            int n = r / BROWS_PER_IMG;
            int j = r - n * BROWS_PER_IMG;
            int h, w;
            if      (j < 58)  { h = 0;             w = j; }
            else if (j < 116) { h = 57;            w = j - 58; }
            else if (j < 172) { h = 1 + (j - 116); w = 0; }
            else              { h = 1 + (j - 172); w = 57; }
            row = ((size_t)(n * HP + h)) * WP + w;
        }
        // one row = 256 bf16 = 512B = 32 x float4
        reinterpret_cast<float4*>(g_xb + row * 256)[lane] = make_float4(0.f, 0.f, 0.f, 0.f);
    }
    if (blockIdx.x == 0 && threadIdx.x < 256) {
        g_sum[threadIdx.x] = 0;
        g_sumsq[threadIdx.x] = 0;
    }
}

// -------- kernel 1: binarize+transpose x NCHW(f32) -> padded NHWC(bf16 +-1) --------
__global__ void pack_x_kernel(const float* __restrict__ x) {
    __shared__ __nv_bfloat16 t[32][34];
    const int tx = threadIdx.x, ty = threadIdx.y;
    const int bz = blockIdx.z;              // n*56 + h
    const int n = bz / 56, h = bz % 56;
    const int w0 = blockIdx.x * 32, c0 = blockIdx.y * 32;
    const __nv_bfloat16 P1 = __float2bfloat16(1.0f);
    const __nv_bfloat16 M1 = __float2bfloat16(-1.0f);
#pragma unroll
    for (int j = 0; j < 4; j++) {
        int c = c0 + ty + j * 8;
        int w = w0 + tx;
        if (w < W) {
            float v = x[(((size_t)n * C + c) * H + h) * W + w];
            t[ty + j * 8][tx] = (v >= 0.f) ? P1 : M1;
        }
    }
    __syncthreads();
#pragma unroll
    for (int j = 0; j < 4; j++) {
        int wl = ty + j * 8;
        int w = w0 + wl;
        if (w < W) {
            int c = c0 + tx;
            g_xb[(((size_t)(n * HP + h + 1)) * WP + (w + 1)) * C + c] = t[tx][wl];
        }
    }
}

// -------- kernel 2: binarize w OIHW -> [tap][cout][cin] bf16 --------
__global__ void pack_w_kernel(const float* __restrict__ w) {
    int g = blockIdx.x * blockDim.x + threadIdx.x;     // co*256+ci
    if (g >= 65536) return;
    const float* wp = w + (size_t)g * 9;
    const __nv_bfloat16 P1 = __float2bfloat16(1.0f);
    const __nv_bfloat16 M1 = __float2bfloat16(-1.0f);
#pragma unroll
    for (int t = 0; t < 9; t++) {
        g_wb[(size_t)t * 65536 + g] = (wp[t] >= 0.f) ? P1 : M1;
    }
}

// -------- kernel 3: implicit-GEMM binary conv (bf16 HMMA, SW128, 3-stage, 1 sync/iter) --------
__global__ void __launch_bounds__(256, 2) conv_kernel() {
    extern __shared__ __align__(1024) char sm[];   // NS stages: [A 16KB | B 16KB]
    const int tid = threadIdx.x;
    const int lane = tid & 31;
    const int warp = tid >> 5;
    const int wm = warp & 1;       // 2 warps along M (64 rows each)
    const int wn = warp >> 1;      // 4 warps along N (32 cols each)
    const size_t mbase = (size_t)blockIdx.x * BM;
    const int nbase = blockIdx.y * BN;

    float acc[4][4][4];
#pragma unroll
    for (int a = 0; a < 4; a++)
#pragma unroll
        for (int b = 0; b < 4; b++)
#pragma unroll
            for (int c = 0; c < 4; c++) acc[a][b][c] = 0.f;

    const uint32_t smbase = smem_u32(sm);

    // producer: all 256 threads; per stage 2048 x 16B (A then B). SW128 xor swizzle.
    auto issue_stage = [&](int s, int it) {
        const int t = it >> 2;                 // tap 0..8
        const int kc = (it & 3) * BKE;         // k-element offset within 256
        const int off = (t / 3) * WP + (t % 3);
        const uint32_t stA = smbase + (uint32_t)s * STAGE_BYTES;
        const uint32_t stB = stA + 16384u;
        const __nv_bfloat16* gA = g_xb + (mbase + (size_t)off) * 256 + kc;
        const __nv_bfloat16* gB = g_wb + (size_t)t * 65536 + (size_t)nbase * 256 + kc;
#pragma unroll
        for (int i = 0; i < 4; ++i) {
            int q = i * 256 + tid;             // 0..1023
            int row = q >> 3, c16 = q & 7;     // 8 x 16B per 128B row
            uint32_t dsto = (uint32_t)(row * 128 + ((c16 ^ (row & 7)) * 16));
            cpasync16(stA + dsto, gA + (size_t)row * 256 + c16 * 8);
        }
#pragma unroll
        for (int i = 0; i < 4; ++i) {
            int q = i * 256 + tid;
            int row = q >> 3, c16 = q & 7;
            uint32_t dsto = (uint32_t)(row * 128 + ((c16 ^ (row & 7)) * 16));
            cpasync16(stB + dsto, gB + (size_t)row * 256 + c16 * 8);
        }
        cpcommit();
    };

    issue_stage(0, 0);
    issue_stage(1, 1);

    for (int it = 0; it < CHUNKS; ++it) {
        const int s = it % NS;
        if (it == CHUNKS - 1) { cpwait<0>(); } else { cpwait<1>(); }
        __syncthreads();
        // prefetch next stage early (writes stage (s+2)%3 = last iteration's compute stage;
        // the barrier above guarantees everyone is done with it)
        if (it + 2 < CHUNKS) issue_stage((it + 2) % NS, it + 2);

        const uint32_t stA = smbase + (uint32_t)s * STAGE_BYTES;
        const uint32_t stB = stA + 16384u;
#pragma unroll
        for (int kf = 0; kf < 4; ++kf) {
            uint32_t a[4][4], b[2][4];
            const int chunk = kf * 2 + (lane >> 4);   // 16B chunk 0..7 within 128B row
#pragma unroll
            for (int mf = 0; mf < 4; ++mf) {
                int row = wm * 64 + mf * 16 + (lane & 15);
                ldsm4(a[mf][0], a[mf][1], a[mf][2], a[mf][3],
                      stA + (uint32_t)(row * 128 + ((chunk ^ (row & 7)) * 16)));
            }
#pragma unroll
            for (int nh = 0; nh < 2; ++nh) {
                int row = wn * 32 + nh * 16 + (lane & 15);
                ldsm4(b[nh][0], b[nh][1], b[nh][2], b[nh][3],
                      stB + (uint32_t)(row * 128 + ((chunk ^ (row & 7)) * 16)));
            }
#pragma unroll
            for (int mf = 0; mf < 4; ++mf)
#pragma unroll
                for (int nf = 0; nf < 4; ++nf) {
                    int nh = nf >> 1, sel = nf & 1;
                    mma16816(acc[mf][nf], a[mf], b[nh][sel], b[nh][sel | 2]);
                }
        }
    }

    // epilogue: exact integer conv results -> int16 [m][cout]
#pragma unroll
    for (int mf = 0; mf < 4; ++mf) {
        size_t m0 = mbase + wm * 64 + mf * 16 + (lane >> 2);
#pragma unroll
        for (int nf = 0; nf < 4; ++nf) {
            int co = nbase + wn * 32 + nf * 8 + (lane & 3) * 2;
            short2 v0 = make_short2((short)__float2int_rn(acc[mf][nf][0]),
                                    (short)__float2int_rn(acc[mf][nf][1]));
            short2 v1 = make_short2((short)__float2int_rn(acc[mf][nf][2]),
                                    (short)__float2int_rn(acc[mf][nf][3]));
            *reinterpret_cast<short2*>(&g_y[m0 * 256 + co]) = v0;
            *reinterpret_cast<short2*>(&g_y[(m0 + 8) * 256 + co]) = v1;
        }
    }
}

// -------- kernel 4: per-channel integer sums over VALID pixels (deterministic) --------
__global__ void stats_kernel() {
    const int co = threadIdx.x;          // 256 threads = 256 channels
    const int b = blockIdx.x;            // 256 blocks x 392 rows
    int sum = 0;
    long long sq = 0;
    for (int r = 0; r < 392; r++) {
        int v = b * 392 + r;
        int n = v / 3136;
        int rem = v - n * 3136;
        int h = rem / 56;
        int w = rem - h * 56;
        size_t m = ((size_t)(n * HP + h)) * WP + w;
        int s = g_y[m * 256 + co];
        sum += s;
        sq += (long long)(s * s);
    }
    atomicAdd(&g_sum[co], sum);
    atomicAdd(reinterpret_cast<unsigned long long*>(&g_sumsq[co]), (unsigned long long)sq);
}

// -------- kernel 5: finalize BN params --------
__global__ void finalize_kernel(const float* __restrict__ gamma, const float* __restrict__ beta) {
    int c = threadIdx.x;
    const double n = (double)NVALID;
    double mean = (double)g_sum[c] / n;
    double var = (double)g_sumsq[c] / n - mean * mean;
    float inv = rsqrtf((float)var + 1e-5f);
    float sc = gamma[c] * inv;
    g_scale[c] = sc;
    g_shift[c] = beta[c] - (float)mean * sc;
}

// -------- kernel 6: normalize + transpose [m][cout] -> NCHW f32 output --------
__global__ void normalize_kernel(float* __restrict__ out) {
    __shared__ float t[32][33];
    const int tx = threadIdx.x, ty = threadIdx.y;
    const int bz = blockIdx.z;            // n*56 + h
    const int n = bz / 56, h = bz % 56;
    const int w0 = blockIdx.x * 32, c0 = blockIdx.y * 32;
    const size_t m0 = ((size_t)(n * HP + h)) * WP;
#pragma unroll
    for (int j = 0; j < 4; j++) {
        int wl = ty + j * 8;
        int w = w0 + wl;
        if (w < W) {
            t[wl][tx] = (float)g_y[(m0 + w) * 256 + c0 + tx];
        }
    }
    __syncthreads();
#pragma unroll
    for (int j = 0; j < 4; j++) {
        int cl = ty + j * 8;
        int c = c0 + cl;
        int w = w0 + tx;
        if (w < W) {
            out[(((size_t)n * C + c) * H + h) * W + w] = t[tx][cl] * g_scale[c] + g_shift[c];
        }
    }
}

extern "C" void kernel_launch(void* const* d_in, const int* in_sizes, int n_in,
                              void* d_out, int out_size) {
    const float* x     = (const float*)d_in[0];
    const float* w     = (const float*)d_in[1];
    const float* gamma = (const float*)d_in[2];
    const float* beta  = (const float*)d_in[3];
    float* out = (float*)d_out;
    (void)in_sizes; (void)n_in; (void)out_size;

    // 0) zero border/pad rows of xb + stats accumulators
    zero_border_kernel<<<(BROWS_TOTAL + 7) / 8, 256>>>();
    // 1) binarize/pad/transpose x (fills all interior rows)
    {
        dim3 grid(2, 8, NB * H);
        dim3 block(32, 8);
        pack_x_kernel<<<grid, block>>>(x);
    }
    // 2) binarize w
    pack_w_kernel<<<256, 256>>>(w);
    // 3) conv (bf16 HMMA implicit GEMM, SW128, 3-stage pipeline)
    {
        static bool attr_set = false;
        if (!attr_set) {
            cudaFuncSetAttribute(conv_kernel, cudaFuncAttributeMaxDynamicSharedMemorySize, DYNSMEM);
            attr_set = true;
        }
        dim3 grid(MP / BM, 256 / BN);   // 841 x 2
        conv_kernel<<<grid, 256, DYNSMEM>>>();
    }
    // 4) per-channel sums
    stats_kernel<<<256, 256>>>();
    // 5) BN params
    finalize_kernel<<<1, 256>>>(gamma, beta);
    // 6) normalize + layout back to NCHW
    {
        dim3 grid(2, 8, NB * H);
        dim3 block(32, 8);
        normalize_kernel<<<grid, block>>>(out);
    }
}

// round 13
// speedup vs baseline: 2.3766x; 1.1694x over previous
#include <cuda_runtime.h>
#include <cuda_bf16.h>
#include <cstdint>

// Problem dims
#define NB   32
#define C    256
#define H    56
#define W    56
#define HP   58
#define WP   58
#define MP   (NB*HP*WP)        // 107648 padded-flat rows (841*128)
#define MPAD 384               // overrun rows for tap offsets (max 118)
#define NVALID (NB*H*W)        // 100352

// GEMM tiling (bf16 HMMA path)
#define BM 128
#define BN 128
#define BKE 64                 // k-elements per chunk (=128 bytes bf16)
#define NS 3                   // cp.async pipeline stages
#define CHUNKS 36              // 9 taps * 4 k-chunks of 64
#define STAGE_BYTES 32768      // A 128x128B + B 128x128B
#define DYNSMEM (NS*STAGE_BYTES)

// -------- device scratch (no allocations allowed) --------
__device__ __align__(1024) __nv_bfloat16 g_xb[(size_t)(MP + MPAD) * C];  // padded NHWC +-1
__device__ __align__(1024) __nv_bfloat16 g_wb[9 * 256 * 256];            // [tap][cout][cin]
__device__ __align__(1024) short g_y[(size_t)MP * 256];                  // conv result (exact ints)
__device__ int       g_sum[256];
__device__ long long g_sumsq[256];
__device__ float     g_scale[256];
__device__ float     g_shift[256];

// -------- asm helpers --------
__device__ __forceinline__ uint32_t smem_u32(const void* p) {
    return (uint32_t)__cvta_generic_to_shared(p);
}
__device__ __forceinline__ void ldsm4(uint32_t& r0, uint32_t& r1, uint32_t& r2, uint32_t& r3, uint32_t a) {
    asm volatile("ldmatrix.sync.aligned.m8n8.x4.shared.b16 {%0,%1,%2,%3}, [%4];"
                 : "=r"(r0), "=r"(r1), "=r"(r2), "=r"(r3) : "r"(a));
}
__device__ __forceinline__ void mma16816(float* d, const uint32_t* a, uint32_t b0, uint32_t b1) {
    asm volatile("mma.sync.aligned.m16n8k16.row.col.f32.bf16.bf16.f32 "
                 "{%0,%1,%2,%3},{%4,%5,%6,%7},{%8,%9},{%0,%1,%2,%3};"
                 : "+f"(d[0]), "+f"(d[1]), "+f"(d[2]), "+f"(d[3])
                 : "r"(a[0]), "r"(a[1]), "r"(a[2]), "r"(a[3]), "r"(b0), "r"(b1));
}
__device__ __forceinline__ void cpasync16(uint32_t dst, const void* src) {
    asm volatile("cp.async.cg.shared.global [%0], [%1], 16;" :: "r"(dst), "l"(src));
}
__device__ __forceinline__ void cpcommit() { asm volatile("cp.async.commit_group;"); }
template <int N> __device__ __forceinline__ void cpwait() { asm volatile("cp.async.wait_group %0;" :: "n"(N)); }

// -------- kernel 0: zero ONLY border/pad rows of xb + stats accumulators --------
#define BROWS_PER_IMG 228
#define BROWS_TOTAL (NB*BROWS_PER_IMG + MPAD)     // 7680
__global__ void zero_border_kernel() {
    const int warp = threadIdx.x >> 5;
    const int lane = threadIdx.x & 31;
    const int r = blockIdx.x * 8 + warp;
    if (r < BROWS_TOTAL) {
        size_t row;
        if (r >= NB * BROWS_PER_IMG) {
            row = (size_t)MP + (r - NB * BROWS_PER_IMG);
        } else {
            int n = r / BROWS_PER_IMG;
            int j = r - n * BROWS_PER_IMG;
            int h, w;
            if      (j < 58)  { h = 0;             w = j; }
            else if (j < 116) { h = 57;            w = j - 58; }
            else if (j < 172) { h = 1 + (j - 116); w = 0; }
            else              { h = 1 + (j - 172); w = 57; }
            row = ((size_t)(n * HP + h)) * WP + w;
        }
        reinterpret_cast<float4*>(g_xb + row * 256)[lane] = make_float4(0.f, 0.f, 0.f, 0.f);
    }
    if (blockIdx.x == 0 && threadIdx.x < 256) {
        g_sum[threadIdx.x] = 0;
        g_sumsq[threadIdx.x] = 0;
    }
}

// -------- kernel 1: binarize+transpose x NCHW(f32) -> padded NHWC(bf16 +-1), 128B stores --------
__global__ void pack_x_kernel(const float* __restrict__ x) {
    __shared__ unsigned short t[64][33];            // [c][w], sign bits as bf16 pattern
    const int tx = threadIdx.x, ty = threadIdx.y;
    const int bz = blockIdx.z;                      // n*56 + h
    const int n = bz / 56, h = bz % 56;
    const int w0 = blockIdx.x * 32, c0 = blockIdx.y * 64;
#pragma unroll
    for (int j = 0; j < 8; j++) {
        int cl = ty + j * 8;
        int w = w0 + tx;
        if (w < W) {
            float v = x[(((size_t)n * C + (c0 + cl)) * H + h) * W + w];
            t[cl][tx] = (v >= 0.f) ? 0x3F80u : 0xBF80u;   // bf16 +1 / -1
        }
    }
    __syncthreads();
#pragma unroll
    for (int j = 0; j < 4; j++) {
        int wl = ty + j * 8;
        int w = w0 + wl;
        if (w < W) {
            uint32_t v = (uint32_t)t[2 * tx][wl] | ((uint32_t)t[2 * tx + 1][wl] << 16);
            *reinterpret_cast<uint32_t*>(
                &g_xb[(((size_t)(n * HP + h + 1)) * WP + (w + 1)) * 256 + c0 + 2 * tx]) = v;
        }
    }
}

// -------- kernel 2: binarize w OIHW -> [tap][cout][cin] bf16 --------
__global__ void pack_w_kernel(const float* __restrict__ w) {
    int g = blockIdx.x * blockDim.x + threadIdx.x;     // co*256+ci
    if (g >= 65536) return;
    const float* wp = w + (size_t)g * 9;
    const __nv_bfloat16 P1 = __float2bfloat16(1.0f);
    const __nv_bfloat16 M1 = __float2bfloat16(-1.0f);
#pragma unroll
    for (int t = 0; t < 9; t++) {
        g_wb[(size_t)t * 65536 + g] = (wp[t] >= 0.f) ? P1 : M1;
    }
}

// -------- kernel 3: conv (bf16 HMMA, SW128, 3-stage, delta-pointer producers, fused BN stats) -----
__global__ void __launch_bounds__(256, 2) conv_kernel() {
    extern __shared__ __align__(1024) char sm[];   // NS stages: [A 16KB | B 16KB]
    __shared__ int s_red[2][128];                  // fused-stats reduction (sum, sumsq)
    const int tid = threadIdx.x;
    const int lane = tid & 31;
    const int warp = tid >> 5;
    const int wm = warp & 1;       // 2 warps along M (64 rows each)
    const int wn = warp >> 1;      // 4 warps along N (32 cols each)
    const size_t mbase = (size_t)blockIdx.x * BM;
    const int nbase = blockIdx.y * BN;

    if (tid < 256) reinterpret_cast<int*>(s_red)[tid] = 0;   // ordered by mainloop barriers

    float acc[4][4][4];
#pragma unroll
    for (int a = 0; a < 4; a++)
#pragma unroll
        for (int b = 0; b < 4; b++)
#pragma unroll
            for (int c = 0; c < 4; c++) acc[a][b][c] = 0.f;

    const uint32_t smbase = smem_u32(sm);

    // ---- hoisted per-thread producer constants ----
    uint32_t dsto[4];    // swizzled smem byte offset (same for A and B)
    uint32_t aoff[4];    // element offset within tile (row*256 + c16*8)
#pragma unroll
    for (int i = 0; i < 4; ++i) {
        int q = i * 256 + tid;                 // 0..1023
        int row = q >> 3, c16 = q & 7;
        dsto[i] = (uint32_t)(row * 128 + ((c16 ^ (row & 7)) * 16));
        aoff[i] = (uint32_t)(row * 256 + c16 * 8);
    }
    // running tile pointers (advance by delta schedule; no per-iteration IMAD chains)
    const __nv_bfloat16* pA = g_xb + mbase * 256;
    const __nv_bfloat16* pB = g_wb + (size_t)nbase * 256;
    int itn = 0;

    auto issue_stage = [&](int s) {
        const uint32_t stA = smbase + (uint32_t)s * STAGE_BYTES;
#pragma unroll
        for (int i = 0; i < 4; ++i) cpasync16(stA + dsto[i], pA + aoff[i]);
#pragma unroll
        for (int i = 0; i < 4; ++i) cpasync16(stA + 16384u + dsto[i], pB + aoff[i]);
        cpcommit();
        // advance to next chunk: +64 elems within tap; tap boundary every 4 chunks
        ++itn;
        if ((itn & 3) == 0) {
            int t = itn >> 2;
            pA += (t % 3 == 0) ? 14144 : 64;   // (WP-2)*256-192 : 256-192
            pB += 65344;                        // 65536-192
        } else {
            pA += 64; pB += 64;
        }
    };

    issue_stage(0);
    issue_stage(1);

    for (int it = 0; it < CHUNKS; ++it) {
        const int s = it % NS;
        if (it == CHUNKS - 1) { cpwait<0>(); } else { cpwait<1>(); }
        __syncthreads();
        if (it + 2 < CHUNKS) issue_stage((it + 2) % NS);

        const uint32_t stA = smbase + (uint32_t)s * STAGE_BYTES;
        const uint32_t stB = stA + 16384u;
#pragma unroll
        for (int kf = 0; kf < 4; ++kf) {
            uint32_t a[4][4], b[2][4];
            const int chunk = kf * 2 + (lane >> 4);   // 16B chunk 0..7 within 128B row
#pragma unroll
            for (int mf = 0; mf < 4; ++mf) {
                int row = wm * 64 + mf * 16 + (lane & 15);
                ldsm4(a[mf][0], a[mf][1], a[mf][2], a[mf][3],
                      stA + (uint32_t)(row * 128 + ((chunk ^ (row & 7)) * 16)));
            }
#pragma unroll
            for (int nh = 0; nh < 2; ++nh) {
                int row = wn * 32 + nh * 16 + (lane & 15);
                ldsm4(b[nh][0], b[nh][1], b[nh][2], b[nh][3],
                      stB + (uint32_t)(row * 128 + ((chunk ^ (row & 7)) * 16)));
            }
#pragma unroll
            for (int mf = 0; mf < 4; ++mf)
#pragma unroll
                for (int nf = 0; nf < 4; ++nf) {
                    int nh = nf >> 1, sel = nf & 1;
                    mma16816(acc[mf][nf], a[mf], b[nh][sel], b[nh][sel | 2]);
                }
        }
    }

    // ---- epilogue: store int16 results + fused BN partial stats ----
    int ssum[4][2] = {{0,0},{0,0},{0,0},{0,0}};
    int ssq [4][2] = {{0,0},{0,0},{0,0},{0,0}};
#pragma unroll
    for (int mf = 0; mf < 4; ++mf) {
        size_t m0 = mbase + wm * 64 + mf * 16 + (lane >> 2);
        int rem0 = (int)(m0 % (HP * WP));
        int rem1 = (int)((m0 + 8) % (HP * WP));
        bool v0 = (rem0 / WP < 56) && (rem0 % WP < 56);
        bool v1 = (rem1 / WP < 56) && (rem1 % WP < 56);
#pragma unroll
        for (int nf = 0; nf < 4; ++nf) {
            int co = nbase + wn * 32 + nf * 8 + (lane & 3) * 2;
            int i0 = __float2int_rn(acc[mf][nf][0]);
            int i1 = __float2int_rn(acc[mf][nf][1]);
            int i2 = __float2int_rn(acc[mf][nf][2]);
            int i3 = __float2int_rn(acc[mf][nf][3]);
            *reinterpret_cast<short2*>(&g_y[m0 * 256 + co]) = make_short2((short)i0, (short)i1);
            *reinterpret_cast<short2*>(&g_y[(m0 + 8) * 256 + co]) = make_short2((short)i2, (short)i3);
            if (v0) { ssum[nf][0] += i0; ssq[nf][0] += i0 * i0;
                      ssum[nf][1] += i1; ssq[nf][1] += i1 * i1; }
            if (v1) { ssum[nf][0] += i2; ssq[nf][0] += i2 * i2;
                      ssum[nf][1] += i3; ssq[nf][1] += i3 * i3; }
        }
    }
    // butterfly-reduce over the 8 quad-rows (lane bits 2..4); totals land in every lane
#pragma unroll
    for (int nf = 0; nf < 4; ++nf)
#pragma unroll
        for (int c = 0; c < 2; ++c) {
#pragma unroll
            for (int off = 4; off < 32; off <<= 1) {
                ssum[nf][c] += __shfl_xor_sync(0xFFFFFFFFu, ssum[nf][c], off);
                ssq [nf][c] += __shfl_xor_sync(0xFFFFFFFFu, ssq [nf][c], off);
            }
        }
    if (lane < 4) {
#pragma unroll
        for (int nf = 0; nf < 4; ++nf)
#pragma unroll
            for (int c = 0; c < 2; ++c) {
                int cl = wn * 32 + nf * 8 + lane * 2 + c;
                atomicAdd(&s_red[0][cl], ssum[nf][c]);
                atomicAdd(&s_red[1][cl], ssq[nf][c]);
            }
    }
    __syncthreads();
    if (tid < 128) {
        atomicAdd(&g_sum[nbase + tid], s_red[0][tid]);
        atomicAdd(reinterpret_cast<unsigned long long*>(&g_sumsq[nbase + tid]),
                  (unsigned long long)(long long)s_red[1][tid]);
    }
}

// -------- kernel 5: finalize BN params --------
__global__ void finalize_kernel(const float* __restrict__ gamma, const float* __restrict__ beta) {
    int c = threadIdx.x;
    const double n = (double)NVALID;
    double mean = (double)g_sum[c] / n;
    double var = (double)g_sumsq[c] / n - mean * mean;
    float inv = rsqrtf((float)var + 1e-5f);
    float sc = gamma[c] * inv;
    g_scale[c] = sc;
    g_shift[c] = beta[c] - (float)mean * sc;
}

// -------- kernel 6: normalize + transpose [m][cout] -> NCHW f32 output (128B loads) --------
__global__ void normalize_kernel(float* __restrict__ out) {
    __shared__ float t[32][65];                   // [w][c]
    const int tx = threadIdx.x, ty = threadIdx.y;
    const int bz = blockIdx.z;                    // n*56 + h
    const int n = bz / 56, h = bz % 56;
    const int w0 = blockIdx.x * 32, c0 = blockIdx.y * 64;
    const size_t m0 = ((size_t)(n * HP + h)) * WP;
#pragma unroll
    for (int j = 0; j < 4; j++) {
        int wl = ty + j * 8;
        int w = w0 + wl;
        if (w < W) {
            short2 p = *reinterpret_cast<const short2*>(&g_y[(m0 + w) * 256 + c0 + 2 * tx]);
            t[wl][2 * tx]     = (float)p.x;
            t[wl][2 * tx + 1] = (float)p.y;
        }
    }
    __syncthreads();
#pragma unroll
    for (int j = 0; j < 8; j++) {
        int cl = ty + j * 8;
        int c = c0 + cl;
        int w = w0 + tx;
        if (w < W) {
            out[(((size_t)n * C + c) * H + h) * W + w] = t[tx][cl] * g_scale[c] + g_shift[c];
        }
    }
}

extern "C" void kernel_launch(void* const* d_in, const int* in_sizes, int n_in,
                              void* d_out, int out_size) {
    const float* x     = (const float*)d_in[0];
    const float* w     = (const float*)d_in[1];
    const float* gamma = (const float*)d_in[2];
    const float* beta  = (const float*)d_in[3];
    float* out = (float*)d_out;
    (void)in_sizes; (void)n_in; (void)out_size;

    // 0) zero border/pad rows of xb + stats accumulators
    zero_border_kernel<<<(BROWS_TOTAL + 7) / 8, 256>>>();
    // 1) binarize/pad/transpose x (fills all interior rows)
    {
        dim3 grid(2, 4, NB * H);
        dim3 block(32, 8);
        pack_x_kernel<<<grid, block>>>(x);
    }
    // 2) binarize w
    pack_w_kernel<<<256, 256>>>(w);
    // 3) conv (bf16 HMMA implicit GEMM, SW128, 3-stage pipeline, fused stats)
    {
        static bool attr_set = false;
        if (!attr_set) {
            cudaFuncSetAttribute(conv_kernel, cudaFuncAttributeMaxDynamicSharedMemorySize, DYNSMEM);
            attr_set = true;
        }
        dim3 grid(MP / BM, 256 / BN);   // 841 x 2
        conv_kernel<<<grid, 256, DYNSMEM>>>();
    }
    // 4) BN params (stats already accumulated by conv epilogue)
    finalize_kernel<<<1, 256>>>(gamma, beta);
    // 5) normalize + layout back to NCHW
    {
        dim3 grid(2, 4, NB * H);
        dim3 block(32, 8);
        normalize_kernel<<<grid, block>>>(out);
    }
}

// round 16
// speedup vs baseline: 2.3901x; 1.0057x over previous
#include <cuda_runtime.h>
#include <cuda_bf16.h>
#include <cstdint>

// Problem dims
#define NB   32
#define C    256
#define H    56
#define W    56
#define HP   58
#define WP   58
#define MP   (NB*HP*WP)        // 107648 padded-flat rows (841*128)
#define MPAD 384               // overrun rows for tap offsets (max 118)
#define NVALID (NB*H*W)        // 100352

// GEMM tiling (bf16 HMMA path)
#define BM 128
#define BN 128
#define BKE 64                 // k-elements per chunk (=128 bytes bf16)
#define NS 3                   // cp.async pipeline stages
#define CHUNKS 36              // 9 taps * 4 k-chunks of 64
#define NBLK (CHUNKS/NS)       // 12
#define STAGE_BYTES 32768      // A 128x128B + B 128x128B
#define DYNSMEM (NS*STAGE_BYTES)

// -------- device scratch (no allocations allowed) --------
__device__ __align__(1024) __nv_bfloat16 g_xb[(size_t)(MP + MPAD) * C];  // padded NHWC +-1
__device__ __align__(1024) __nv_bfloat16 g_wb[9 * 256 * 256];            // [tap][cout][cin]
__device__ __align__(1024) short g_y[(size_t)MP * 256];                  // conv result (exact ints)
__device__ int       g_sum[256];
__device__ long long g_sumsq[256];
__device__ float     g_scale[256];
__device__ float     g_shift[256];

// -------- asm helpers --------
__device__ __forceinline__ uint32_t smem_u32(const void* p) {
    return (uint32_t)__cvta_generic_to_shared(p);
}
__device__ __forceinline__ void ldsm4(uint32_t& r0, uint32_t& r1, uint32_t& r2, uint32_t& r3, uint32_t a) {
    asm volatile("ldmatrix.sync.aligned.m8n8.x4.shared.b16 {%0,%1,%2,%3}, [%4];"
                 : "=r"(r0), "=r"(r1), "=r"(r2), "=r"(r3) : "r"(a));
}
__device__ __forceinline__ void mma16816(float* d, const uint32_t* a, uint32_t b0, uint32_t b1) {
    asm volatile("mma.sync.aligned.m16n8k16.row.col.f32.bf16.bf16.f32 "
                 "{%0,%1,%2,%3},{%4,%5,%6,%7},{%8,%9},{%0,%1,%2,%3};"
                 : "+f"(d[0]), "+f"(d[1]), "+f"(d[2]), "+f"(d[3])
                 : "r"(a[0]), "r"(a[1]), "r"(a[2]), "r"(a[3]), "r"(b0), "r"(b1));
}
__device__ __forceinline__ void cpasync16(uint32_t dst, const void* src) {
    asm volatile("cp.async.cg.shared.global [%0], [%1], 16;" :: "r"(dst), "l"(src));
}
__device__ __forceinline__ void cpcommit() { asm volatile("cp.async.commit_group;"); }
template <int N> __device__ __forceinline__ void cpwait() { asm volatile("cp.async.wait_group %0;" :: "n"(N)); }

// -------- kernel 0: zero ONLY border/pad rows of xb + stats accumulators --------
#define BROWS_PER_IMG 228
#define BROWS_TOTAL (NB*BROWS_PER_IMG + MPAD)     // 7680
__global__ void zero_border_kernel() {
    const int warp = threadIdx.x >> 5;
    const int lane = threadIdx.x & 31;
    const int r = blockIdx.x * 8 + warp;
    if (r < BROWS_TOTAL) {
        size_t row;
        if (r >= NB * BROWS_PER_IMG) {
            row = (size_t)MP + (r - NB * BROWS_PER_IMG);
        } else {
            int n = r / BROWS_PER_IMG;
            int j = r - n * BROWS_PER_IMG;
            int h, w;
            if      (j < 58)  { h = 0;             w = j; }
            else if (j < 116) { h = 57;            w = j - 58; }
            else if (j < 172) { h = 1 + (j - 116); w = 0; }
            else              { h = 1 + (j - 172); w = 57; }
            row = ((size_t)(n * HP + h)) * WP + w;
        }
        reinterpret_cast<float4*>(g_xb + row * 256)[lane] = make_float4(0.f, 0.f, 0.f, 0.f);
    }
    if (blockIdx.x == 0 && threadIdx.x < 256) {
        g_sum[threadIdx.x] = 0;
        g_sumsq[threadIdx.x] = 0;
    }
}

// -------- kernel 1: binarize+transpose x NCHW(f32) -> padded NHWC(bf16 +-1), 128B stores --------
__global__ void pack_x_kernel(const float* __restrict__ x) {
    __shared__ unsigned short t[64][33];            // [c][w], sign bits as bf16 pattern
    const int tx = threadIdx.x, ty = threadIdx.y;
    const int bz = blockIdx.z;                      // n*56 + h
    const int n = bz / 56, h = bz % 56;
    const int w0 = blockIdx.x * 32, c0 = blockIdx.y * 64;
#pragma unroll
    for (int j = 0; j < 8; j++) {
        int cl = ty + j * 8;
        int w = w0 + tx;
        if (w < W) {
            float v = x[(((size_t)n * C + (c0 + cl)) * H + h) * W + w];
            t[cl][tx] = (v >= 0.f) ? 0x3F80u : 0xBF80u;   // bf16 +1 / -1
        }
    }
    __syncthreads();
#pragma unroll
    for (int j = 0; j < 4; j++) {
        int wl = ty + j * 8;
        int w = w0 + wl;
        if (w < W) {
            uint32_t v = (uint32_t)t[2 * tx][wl] | ((uint32_t)t[2 * tx + 1][wl] << 16);
            *reinterpret_cast<uint32_t*>(
                &g_xb[(((size_t)(n * HP + h + 1)) * WP + (w + 1)) * 256 + c0 + 2 * tx]) = v;
        }
    }
}

// -------- kernel 2: binarize w OIHW -> [tap][cout][cin] bf16 --------
__global__ void pack_w_kernel(const float* __restrict__ w) {
    int g = blockIdx.x * blockDim.x + threadIdx.x;     // co*256+ci
    if (g >= 65536) return;
    const float* wp = w + (size_t)g * 9;
    const __nv_bfloat16 P1 = __float2bfloat16(1.0f);
    const __nv_bfloat16 M1 = __float2bfloat16(-1.0f);
#pragma unroll
    for (int t = 0; t < 9; t++) {
        g_wb[(size_t)t * 65536 + g] = (wp[t] >= 0.f) ? P1 : M1;
    }
}

// -------- kernel 3: conv (bf16 HMMA, SW128, stage-unrolled 3-deep pipeline, fused BN stats) ------
__global__ void __launch_bounds__(256, 2) conv_kernel() {
    extern __shared__ __align__(1024) char sm[];   // NS stages: [A 16KB | B 16KB]
    __shared__ int s_red[2][128];                  // fused-stats reduction (sum, sumsq)
    const int tid = threadIdx.x;
    const int lane = tid & 31;
    const int warp = tid >> 5;
    const int wm = warp & 1;       // 2 warps along M (64 rows each)
    const int wn = warp >> 1;      // 4 warps along N (32 cols each)
    const size_t mbase = (size_t)blockIdx.x * BM;
    const int nbase = blockIdx.y * BN;

    if (tid < 256) reinterpret_cast<int*>(s_red)[tid] = 0;   // ordered by mainloop barriers

    float acc[4][4][4];
#pragma unroll
    for (int a = 0; a < 4; a++)
#pragma unroll
        for (int b = 0; b < 4; b++)
#pragma unroll
            for (int c = 0; c < 4; c++) acc[a][b][c] = 0.f;

    const uint32_t smbase = smem_u32(sm);

    // ---- hoisted per-thread producer constants ----
    uint32_t dsto[4];    // swizzled smem byte offset (same for A and B)
    uint32_t aoff[4];    // element offset within tile (row*256 + c16*8)
#pragma unroll
    for (int i = 0; i < 4; ++i) {
        int q = i * 256 + tid;                 // 0..1023
        int row = q >> 3, c16 = q & 7;
        dsto[i] = (uint32_t)(row * 128 + ((c16 ^ (row & 7)) * 16));
        aoff[i] = (uint32_t)(row * 256 + c16 * 8);
    }
    // running tile pointers (advance by delta schedule)
    const __nv_bfloat16* pA = g_xb + mbase * 256;
    const __nv_bfloat16* pB = g_wb + (size_t)nbase * 256;
    int itn = 0;

    auto issue_stage = [&](int s) {
        const uint32_t stA = smbase + (uint32_t)s * STAGE_BYTES;
#pragma unroll
        for (int i = 0; i < 4; ++i) cpasync16(stA + dsto[i], pA + aoff[i]);
#pragma unroll
        for (int i = 0; i < 4; ++i) cpasync16(stA + 16384u + dsto[i], pB + aoff[i]);
        cpcommit();
        ++itn;
        if ((itn & 3) == 0) {
            int t = itn >> 2;
            pA += (t % 3 == 0) ? 14144 : 64;   // (WP-2)*256-192 : 256-192
            pB += 65344;                        // 65536-192
        } else {
            pA += 64; pB += 64;
        }
    };

    // consumer helper: compute one stage (s is compile-time at every call site)
    auto compute_stage = [&](const uint32_t stA) {
        const uint32_t stB = stA + 16384u;
#pragma unroll
        for (int kf = 0; kf < 4; ++kf) {
            uint32_t a[4][4], b[2][4];
            const int chunk = kf * 2 + (lane >> 4);   // 16B chunk 0..7 within 128B row
#pragma unroll
            for (int mf = 0; mf < 4; ++mf) {
                int row = wm * 64 + mf * 16 + (lane & 15);
                ldsm4(a[mf][0], a[mf][1], a[mf][2], a[mf][3],
                      stA + (uint32_t)(row * 128 + ((chunk ^ (row & 7)) * 16)));
            }
#pragma unroll
            for (int nh = 0; nh < 2; ++nh) {
                int row = wn * 32 + nh * 16 + (lane & 15);
                ldsm4(b[nh][0], b[nh][1], b[nh][2], b[nh][3],
                      stB + (uint32_t)(row * 128 + ((chunk ^ (row & 7)) * 16)));
            }
#pragma unroll
            for (int mf = 0; mf < 4; ++mf)
#pragma unroll
                for (int nf = 0; nf < 4; ++nf) {
                    int nh = nf >> 1, sel = nf & 1;
                    mma16816(acc[mf][nf], a[mf], b[nh][sel], b[nh][sel | 2]);
                }
        }
    };

    issue_stage(0);
    issue_stage(1);

    // mainloop unrolled by NS: stage index (and thus all smem addresses) compile-time per body
    for (int blk = 0; blk < NBLK; ++blk) {
        const bool lastblk = (blk == NBLK - 1);
#pragma unroll
        for (int s = 0; s < NS; ++s) {
            if (lastblk && s == NS - 1) { cpwait<0>(); } else { cpwait<1>(); }
            __syncthreads();
            if (!lastblk || s == 0) issue_stage((s + 2) % NS);
            compute_stage(smbase + (uint32_t)(s * STAGE_BYTES));
        }
    }

    // ---- epilogue: store int16 results + fused BN partial stats ----
    int ssum[4][2] = {{0,0},{0,0},{0,0},{0,0}};
    int ssq [4][2] = {{0,0},{0,0},{0,0},{0,0}};
#pragma unroll
    for (int mf = 0; mf < 4; ++mf) {
        size_t m0 = mbase + wm * 64 + mf * 16 + (lane >> 2);
        int rem0 = (int)(m0 % (HP * WP));
        int rem1 = (int)((m0 + 8) % (HP * WP));
        bool v0 = (rem0 / WP < 56) && (rem0 % WP < 56);
        bool v1 = (rem1 / WP < 56) && (rem1 % WP < 56);
#pragma unroll
        for (int nf = 0; nf < 4; ++nf) {
            int co = nbase + wn * 32 + nf * 8 + (lane & 3) * 2;
            int i0 = __float2int_rn(acc[mf][nf][0]);
            int i1 = __float2int_rn(acc[mf][nf][1]);
            int i2 = __float2int_rn(acc[mf][nf][2]);
            int i3 = __float2int_rn(acc[mf][nf][3]);
            *reinterpret_cast<short2*>(&g_y[m0 * 256 + co]) = make_short2((short)i0, (short)i1);
            *reinterpret_cast<short2*>(&g_y[(m0 + 8) * 256 + co]) = make_short2((short)i2, (short)i3);
            if (v0) { ssum[nf][0] += i0; ssq[nf][0] += i0 * i0;
                      ssum[nf][1] += i1; ssq[nf][1] += i1 * i1; }
            if (v1) { ssum[nf][0] += i2; ssq[nf][0] += i2 * i2;
                      ssum[nf][1] += i3; ssq[nf][1] += i3 * i3; }
        }
    }
    // butterfly-reduce over the 8 quad-rows (lane bits 2..4); totals land in every lane
#pragma unroll
    for (int nf = 0; nf < 4; ++nf)
#pragma unroll
        for (int c = 0; c < 2; ++c) {
#pragma unroll
            for (int off = 4; off < 32; off <<= 1) {
                ssum[nf][c] += __shfl_xor_sync(0xFFFFFFFFu, ssum[nf][c], off);
                ssq [nf][c] += __shfl_xor_sync(0xFFFFFFFFu, ssq [nf][c], off);
            }
        }
    if (lane < 4) {
#pragma unroll
        for (int nf = 0; nf < 4; ++nf)
#pragma unroll
            for (int c = 0; c < 2; ++c) {
                int cl = wn * 32 + nf * 8 + lane * 2 + c;
                atomicAdd(&s_red[0][cl], ssum[nf][c]);
                atomicAdd(&s_red[1][cl], ssq[nf][c]);
            }
    }
    __syncthreads();
    if (tid < 128) {
        atomicAdd(&g_sum[nbase + tid], s_red[0][tid]);
        atomicAdd(reinterpret_cast<unsigned long long*>(&g_sumsq[nbase + tid]),
                  (unsigned long long)(long long)s_red[1][tid]);
    }
}

// -------- kernel 5: finalize BN params --------
__global__ void finalize_kernel(const float* __restrict__ gamma, const float* __restrict__ beta) {
    int c = threadIdx.x;
    const double n = (double)NVALID;
    double mean = (double)g_sum[c] / n;
    double var = (double)g_sumsq[c] / n - mean * mean;
    float inv = rsqrtf((float)var + 1e-5f);
    float sc = gamma[c] * inv;
    g_scale[c] = sc;
    g_shift[c] = beta[c] - (float)mean * sc;
}

// -------- kernel 6: normalize + transpose [m][cout] -> NCHW f32 output (128B loads) --------
__global__ void normalize_kernel(float* __restrict__ out) {
    __shared__ float t[32][65];                   // [w][c]
    const int tx = threadIdx.x, ty = threadIdx.y;
    const int bz = blockIdx.z;                    // n*56 + h
    const int n = bz / 56, h = bz % 56;
    const int w0 = blockIdx.x * 32, c0 = blockIdx.y * 64;
    const size_t m0 = ((size_t)(n * HP + h)) * WP;
#pragma unroll
    for (int j = 0; j < 4; j++) {
        int wl = ty + j * 8;
        int w = w0 + wl;
        if (w < W) {
            short2 p = *reinterpret_cast<const short2*>(&g_y[(m0 + w) * 256 + c0 + 2 * tx]);
            t[wl][2 * tx]     = (float)p.x;
            t[wl][2 * tx + 1] = (float)p.y;
        }
    }
    __syncthreads();
#pragma unroll
    for (int j = 0; j < 8; j++) {
        int cl = ty + j * 8;
        int c = c0 + cl;
        int w = w0 + tx;
        if (w < W) {
            out[(((size_t)n * C + c) * H + h) * W + w] = t[tx][cl] * g_scale[c] + g_shift[c];
        }
    }
}

extern "C" void kernel_launch(void* const* d_in, const int* in_sizes, int n_in,
                              void* d_out, int out_size) {
    const float* x     = (const float*)d_in[0];
    const float* w     = (const float*)d_in[1];
    const float* gamma = (const float*)d_in[2];
    const float* beta  = (const float*)d_in[3];
    float* out = (float*)d_out;
    (void)in_sizes; (void)n_in; (void)out_size;

    // 0) zero border/pad rows of xb + stats accumulators
    zero_border_kernel<<<(BROWS_TOTAL + 7) / 8, 256>>>();
    // 1) binarize/pad/transpose x (fills all interior rows)
    {
        dim3 grid(2, 4, NB * H);
        dim3 block(32, 8);
        pack_x_kernel<<<grid, block>>>(x);
    }
    // 2) binarize w
    pack_w_kernel<<<256, 256>>>(w);
    // 3) conv (bf16 HMMA implicit GEMM, SW128, stage-unrolled pipeline, fused stats)
    {
        static bool attr_set = false;
        if (!attr_set) {
            cudaFuncSetAttribute(conv_kernel, cudaFuncAttributeMaxDynamicSharedMemorySize, DYNSMEM);
            attr_set = true;
        }
        dim3 grid(MP / BM, 256 / BN);   // 841 x 2
        conv_kernel<<<grid, 256, DYNSMEM>>>();
    }
    // 4) BN params (stats already accumulated by conv epilogue)
    finalize_kernel<<<1, 256>>>(gamma, beta);
    // 5) normalize + layout back to NCHW
    {
        dim3 grid(2, 4, NB * H);
        dim3 block(32, 8);
        normalize_kernel<<<grid, block>>>(out);
    }
}